// round 1
// baseline (speedup 1.0000x reference)
#include <cuda_runtime.h>
#include <math.h>

#define L_  2048
#define E_  1024
#define H_  16
#define D_  64
#define MBL_ 2048

// ---------------- device scratch (static; allocation-free kernel_launch) ---
__device__ float g_q[H_ * L_ * D_];             // [H][L][D]
__device__ float g_k[H_ * L_ * D_];
__device__ float g_v[H_ * L_ * D_];
__device__ float g_ao[L_ * E_];                 // attention out, [L][H*D]
__device__ float g_e[(size_t)H_ * L_ * L_];     // unnormalized exp(s - m_tile)

// ============================================================================
// Classic 128x128x8 fp32 SGEMM core, NT layout: C[M,N] = A[M,K] * B[N,K]^T
// 256 threads, each computes 8x8. A,B rows are K-contiguous (coalesced).
// ============================================================================
struct GemmCore {
    float acc[8][8];
};

__device__ __forceinline__ void gemm_tile_nt(
    const float* __restrict__ A, const float* __restrict__ B,
    int K, int m0, int n0, float acc[8][8], float* sA, float* sB)
{
    int tid  = threadIdx.x;
    int ty   = tid >> 4;            // 0..15
    int tx   = tid & 15;            // 0..15
    int lrow = tid >> 1;            // 0..127
    int lk4  = (tid & 1) * 4;       // 0 or 4

#pragma unroll
    for (int i = 0; i < 8; i++)
#pragma unroll
        for (int j = 0; j < 8; j++) acc[i][j] = 0.f;

    for (int kt = 0; kt < K; kt += 8) {
        float4 av = *(const float4*)(A + (size_t)(m0 + lrow) * K + kt + lk4);
        float4 bv = *(const float4*)(B + (size_t)(n0 + lrow) * K + kt + lk4);
        __syncthreads();
        sA[(lk4 + 0) * 128 + lrow] = av.x;
        sA[(lk4 + 1) * 128 + lrow] = av.y;
        sA[(lk4 + 2) * 128 + lrow] = av.z;
        sA[(lk4 + 3) * 128 + lrow] = av.w;
        sB[(lk4 + 0) * 128 + lrow] = bv.x;
        sB[(lk4 + 1) * 128 + lrow] = bv.y;
        sB[(lk4 + 2) * 128 + lrow] = bv.z;
        sB[(lk4 + 3) * 128 + lrow] = bv.w;
        __syncthreads();
#pragma unroll
        for (int k = 0; k < 8; k++) {
            float a[8], b[8];
            *(float4*)&a[0] = *(float4*)&sA[k * 128 + ty * 8];
            *(float4*)&a[4] = *(float4*)&sA[k * 128 + ty * 8 + 4];
            *(float4*)&b[0] = *(float4*)&sB[k * 128 + tx * 8];
            *(float4*)&b[4] = *(float4*)&sB[k * 128 + tx * 8 + 4];
#pragma unroll
            for (int i = 0; i < 8; i++)
#pragma unroll
                for (int j = 0; j < 8; j++)
                    acc[i][j] += a[i] * b[j];
        }
    }
}

// QKV projections: z selects {Wq,Wk,Wv}; output written in [H][L][D] layout.
__global__ __launch_bounds__(256) void qkv_gemm(
    const float* __restrict__ x,
    const float* __restrict__ Wq,
    const float* __restrict__ Wk,
    const float* __restrict__ Wv)
{
    __shared__ float sA[8 * 128];
    __shared__ float sB[8 * 128];
    const float* B = (blockIdx.z == 0) ? Wq : (blockIdx.z == 1) ? Wk : Wv;
    float* C = (blockIdx.z == 0) ? g_q : (blockIdx.z == 1) ? g_k : g_v;

    int m0 = blockIdx.y * 128;
    int n0 = blockIdx.x * 128;
    float acc[8][8];
    gemm_tile_nt(x, B, E_, m0, n0, acc, sA, sB);

    int ty = threadIdx.x >> 4, tx = threadIdx.x & 15;
#pragma unroll
    for (int i = 0; i < 8; i++) {
        int m = m0 + ty * 8 + i;
#pragma unroll
        for (int j4 = 0; j4 < 8; j4 += 4) {
            int n = n0 + tx * 8 + j4;
            float4 v = make_float4(acc[i][j4], acc[i][j4 + 1], acc[i][j4 + 2], acc[i][j4 + 3]);
            // head layout: [h][l][d], h = n/64, d = n%64 (4-elem group stays in head)
            *(float4*)(C + (size_t)(n >> 6) * (L_ * 64) + (size_t)m * 64 + (n & 63)) = v;
        }
    }
}

// Output projection: d_out[L,E] = g_ao @ Wo^T
__global__ __launch_bounds__(256) void out_gemm(
    const float* __restrict__ Wo, float* __restrict__ out)
{
    __shared__ float sA[8 * 128];
    __shared__ float sB[8 * 128];
    int m0 = blockIdx.y * 128;
    int n0 = blockIdx.x * 128;
    float acc[8][8];
    gemm_tile_nt(g_ao, Wo, E_, m0, n0, acc, sA, sB);

    int ty = threadIdx.x >> 4, tx = threadIdx.x & 15;
#pragma unroll
    for (int i = 0; i < 8; i++) {
        int m = m0 + ty * 8 + i;
#pragma unroll
        for (int j4 = 0; j4 < 8; j4 += 4) {
            int n = n0 + tx * 8 + j4;
            *(float4*)(out + (size_t)m * E_ + n) =
                make_float4(acc[i][j4], acc[i][j4 + 1], acc[i][j4 + 2], acc[i][j4 + 3]);
        }
    }
}

// ============================================================================
// Attention kernel. One CTA = (head h, 64-query tile iq). 256 threads.
// Pass 1: online softmax stats (m, Z) per row; stores e = exp(s - m_tile) to
//         g_e and m_tile history to smem.
// Pass 2: p = e * exp(m_tile - m_final) / Z; t = relu(p + tau/idx); O += T @ V.
// ============================================================================
__global__ __launch_bounds__(256) void attn_kernel(
    const float* __restrict__ bias, const float* __restrict__ tau)
{
    __shared__ float QTs[64 * 68];   // pass1: Q^T [d][r]; pass2 reused: T^T [c][r]
    __shared__ float KVs[64 * 68];   // pass1: K^T [d][c]; pass2: V [c][d]
    __shared__ float mrow[64], zrow[64];
    __shared__ float mhist[64 * 32]; // m used when tile jt was exponentiated

    int h  = blockIdx.y;
    int iq = gridDim.x - 1 - blockIdx.x;   // heavy (late) q-tiles launch first
    int q0 = iq * 64;
    int tid = threadIdx.x;
    int ty = tid >> 4, tx = tid & 15;
    float tauh = tau[h];
    const float scale = 0.125f;            // D^-0.5
    int ntiles = iq + 1;

    // ---- load Q tile transposed: QTs[d][r] ----
    const float* qbase = g_q + (size_t)h * L_ * D_ + (size_t)q0 * D_;
#pragma unroll
    for (int p = 0; p < 4; p++) {
        int idx = tid + p * 256;
        int r = idx >> 4;
        int d4 = (idx & 15) * 4;
        float4 v = *(const float4*)(qbase + r * D_ + d4);
        QTs[(d4 + 0) * 68 + r] = v.x;
        QTs[(d4 + 1) * 68 + r] = v.y;
        QTs[(d4 + 2) * 68 + r] = v.z;
        QTs[(d4 + 3) * 68 + r] = v.w;
    }
    if (tid < 64) { mrow[tid] = -INFINITY; zrow[tid] = 0.f; }

    // ==================== PASS 1 ====================
    for (int jt = 0; jt < ntiles; jt++) {
        int k0 = jt * 64;
        const float* kbase = g_k + (size_t)h * L_ * D_ + (size_t)k0 * D_;
        __syncthreads();   // previous tile done reading KVs (+ Q/m/z init visible)
#pragma unroll
        for (int p = 0; p < 4; p++) {
            int idx = tid + p * 256;
            int r = idx >> 4;
            int d4 = (idx & 15) * 4;
            float4 v = *(const float4*)(kbase + r * D_ + d4);
            KVs[(d4 + 0) * 68 + r] = v.x;
            KVs[(d4 + 1) * 68 + r] = v.y;
            KVs[(d4 + 2) * 68 + r] = v.z;
            KVs[(d4 + 3) * 68 + r] = v.w;
        }
        __syncthreads();

        // S = Q K^T  (4x4 per thread)
        float s[4][4];
#pragma unroll
        for (int i = 0; i < 4; i++)
#pragma unroll
            for (int j = 0; j < 4; j++) s[i][j] = 0.f;
#pragma unroll 16
        for (int d = 0; d < 64; d++) {
            float4 a = *(const float4*)&QTs[d * 68 + ty * 4];
            float4 b = *(const float4*)&KVs[d * 68 + tx * 4];
            float av[4] = {a.x, a.y, a.z, a.w};
            float bv[4] = {b.x, b.y, b.z, b.w};
#pragma unroll
            for (int i = 0; i < 4; i++)
#pragma unroll
                for (int j = 0; j < 4; j++)
                    s[i][j] += av[i] * bv[j];
        }

        // scale + bias + causal mask
#pragma unroll
        for (int i = 0; i < 4; i++) {
            int q = q0 + ty * 4 + i;
#pragma unroll
            for (int j = 0; j < 4; j++) {
                int k = k0 + tx * 4 + j;
                int dist = q - k;
                s[i][j] = (dist >= 0) ? (s[i][j] * scale + bias[h * MBL_ + dist])
                                      : -INFINITY;
            }
        }

        // per-row online stats; store e. Row r = ty*4+i lives on a 16-lane
        // half-warp (same ty), so shuffles + the tx==0 write are warp-safe.
#pragma unroll
        for (int i = 0; i < 4; i++) {
            int r = ty * 4 + i;
            float mold = mrow[r];
            float rmax = fmaxf(fmaxf(s[i][0], s[i][1]), fmaxf(s[i][2], s[i][3]));
#pragma unroll
            for (int o = 8; o >= 1; o >>= 1)
                rmax = fmaxf(rmax, __shfl_xor_sync(0xffffffffu, rmax, o));
            float mnew = fmaxf(mold, rmax);
            float e0 = __expf(s[i][0] - mnew);
            float e1 = __expf(s[i][1] - mnew);
            float e2 = __expf(s[i][2] - mnew);
            float e3 = __expf(s[i][3] - mnew);
            *(float4*)(g_e + ((size_t)h * L_ + q0 + r) * L_ + k0 + tx * 4) =
                make_float4(e0, e1, e2, e3);
            float rs = e0 + e1 + e2 + e3;
#pragma unroll
            for (int o = 8; o >= 1; o >>= 1)
                rs += __shfl_xor_sync(0xffffffffu, rs, o);
            if (tx == 0) {
                zrow[r] = zrow[r] * __expf(mold - mnew) + rs;
                mrow[r] = mnew;
                mhist[r * 32 + jt] = mnew;
            }
        }
    }
    __syncthreads();

    // ==================== PASS 2 ====================
    float mfin[4], invz[4], taut[4];
#pragma unroll
    for (int i = 0; i < 4; i++) {
        int r = ty * 4 + i;
        mfin[i] = mrow[r];
        invz[i] = 1.f / zrow[r];
        taut[i] = tauh / (float)(q0 + r + 1);
    }
    float o[4][4];
#pragma unroll
    for (int i = 0; i < 4; i++)
#pragma unroll
        for (int j = 0; j < 4; j++) o[i][j] = 0.f;

    for (int jt = 0; jt < ntiles; jt++) {
        int k0 = jt * 64;
        // rescale stored exponentials, apply elastic-softmax relu
        float t[4][4];
#pragma unroll
        for (int i = 0; i < 4; i++) {
            int r = ty * 4 + i;
            float4 ev = *(const float4*)(g_e + ((size_t)h * L_ + q0 + r) * L_ + k0 + tx * 4);
            float f = __expf(mhist[r * 32 + jt] - mfin[i]) * invz[i];
            t[i][0] = fmaxf(ev.x * f + taut[i], 0.f);
            t[i][1] = fmaxf(ev.y * f + taut[i], 0.f);
            t[i][2] = fmaxf(ev.z * f + taut[i], 0.f);
            t[i][3] = fmaxf(ev.w * f + taut[i], 0.f);
        }
        __syncthreads();   // previous PV done reading QTs(T) & KVs(V)
        // write T transposed: QTs reused as T^T [c][r]
#pragma unroll
        for (int i = 0; i < 4; i++)
#pragma unroll
            for (int j = 0; j < 4; j++)
                QTs[(tx * 4 + j) * 68 + ty * 4 + i] = t[i][j];
        // load V tile direct: KVs[c][d]
        const float* vbase = g_v + (size_t)h * L_ * D_ + (size_t)k0 * D_;
#pragma unroll
        for (int p = 0; p < 4; p++) {
            int idx = tid + p * 256;
            int r = idx >> 4;
            int d4 = (idx & 15) * 4;
            *(float4*)&KVs[r * 68 + d4] = *(const float4*)(vbase + r * D_ + d4);
        }
        __syncthreads();
        // O += T @ V
#pragma unroll 8
        for (int c = 0; c < 64; c++) {
            float4 tv = *(const float4*)&QTs[c * 68 + ty * 4];
            float4 vv = *(const float4*)&KVs[c * 68 + tx * 4];
            float ta[4] = {tv.x, tv.y, tv.z, tv.w};
            float va[4] = {vv.x, vv.y, vv.z, vv.w};
#pragma unroll
            for (int i = 0; i < 4; i++)
#pragma unroll
                for (int j = 0; j < 4; j++)
                    o[i][j] += ta[i] * va[j];
        }
    }

    // write O to g_ao[l][h*64+d]
#pragma unroll
    for (int i = 0; i < 4; i++) {
        int q = q0 + ty * 4 + i;
        *(float4*)(g_ao + (size_t)q * E_ + h * 64 + tx * 4) =
            make_float4(o[i][0], o[i][1], o[i][2], o[i][3]);
    }
}

// ============================================================================
extern "C" void kernel_launch(void* const* d_in, const int* in_sizes, int n_in,
                              void* d_out, int out_size)
{
    (void)in_sizes; (void)n_in; (void)out_size;
    const float* x    = (const float*)d_in[0];
    const float* Wq   = (const float*)d_in[1];
    const float* Wk   = (const float*)d_in[2];
    const float* Wv   = (const float*)d_in[3];
    const float* Wo   = (const float*)d_in[4];
    const float* bias = (const float*)d_in[5];
    const float* tau  = (const float*)d_in[6];
    float* out = (float*)d_out;

    // QKV projections: N tiles x M tiles x {q,k,v}
    qkv_gemm<<<dim3(E_ / 128, L_ / 128, 3), 256>>>(x, Wq, Wk, Wv);
    // Attention
    attn_kernel<<<dim3(L_ / 64, H_), 256>>>(bias, tau);
    // Output projection
    out_gemm<<<dim3(E_ / 128, L_ / 128), 256>>>(Wo, out);
}